// round 17
// baseline (speedup 1.0000x reference)
#include <cuda_runtime.h>
#include <cuda_bf16.h>
#include <math.h>

#define NIN 14
#define NH 256
#define KTOT 10
#define TM 64
#define NTHREADS 512
#define KKX 17              // k-steps for 272-wide input (256 summary + 14 tower + 2 pad)
#define KKH 16              // k-steps for 256-wide hidden
#define XWORDS (4 * KKX * 4 * 32)   // 8704 uint2 (TM/16 = 4 m-tiles)
#define HWORDS (4 * KKH * 4 * 32)   // 8192 uint2

// ---------------------------------------------------------------------------
// Fast split: value = hi(bf16) + lo(bf16); identical numerics to the RN/RN
// two-step split. Word packs a k-pair: low 16 = even-k, high 16 = odd-k.
// uint2: .x = hi-pair word, .y = lo-pair word.
// ---------------------------------------------------------------------------
__device__ __forceinline__ uint2 split2(float v0, float v1) {
    uint2 w;
    asm("cvt.rn.bf16x2.f32 %0, %1, %2;" : "=r"(w.x) : "f"(v1), "f"(v0));
    float h0 = __uint_as_float(w.x << 16);
    float h1 = __uint_as_float(w.x & 0xffff0000u);
    float r0 = v0 - h0;                 // exact (Sterbenz)
    float r1 = v1 - h1;
    asm("cvt.rn.bf16x2.f32 %0, %1, %2;" : "=r"(w.y) : "f"(r1), "f"(r0));
    return w;
}
__device__ __forceinline__ float bf_lo(unsigned w) {
    return __uint_as_float(w << 16);
}
__device__ __forceinline__ float bf_hi(unsigned w) {
    return __uint_as_float(w & 0xffff0000u);
}

// ---------------------------------------------------------------------------
// Fragment-major weight arrays (built once).
// Index: ((kk*32 + ntg)*2 + slot)*32 + lane
//   cols = ntg*8 + (lane>>2), k0 = kk*16 + slot*8 + 2*(lane&3)
//   word = { W[k0][col], W[k0+1][col] }  (hi pair in .x, lo pair in .y)
// ---------------------------------------------------------------------------
__device__ __align__(16) uint2 g_M1[KKX * 2048];
__device__ __align__(16) uint2 g_O1[KKX * 2048];
__device__ __align__(16) uint2 g_M2[KKH * 2048];
__device__ __align__(16) uint2 g_M3[KKH * 2048];
__device__ __align__(16) uint2 g_O2[KKH * 2048];

__global__ void prep_weights(const float* __restrict__ M1w,
                             const float* __restrict__ O1w,
                             const float* __restrict__ M2w,
                             const float* __restrict__ M3w,
                             const float* __restrict__ O2w) {
    int w = blockIdx.x * blockDim.x + threadIdx.x;
    if (w >= KKX * 2048) return;
    int kk   = w >> 11;
    int rem  = w & 2047;
    int ntg  = rem >> 6;
    int slot = (rem >> 5) & 1;
    int lane = rem & 31;
    int k0   = kk * 16 + slot * 8 + 2 * (lane & 3);
    int col  = ntg * 8 + (lane >> 2);

    float a0 = (k0     < 270) ? M1w[k0 * NH + col]       : 0.f;
    float a1 = (k0 + 1 < 270) ? M1w[(k0 + 1) * NH + col] : 0.f;
    g_M1[w] = split2(a0, a1);
    a0 = (k0     < 270) ? O1w[k0 * NH + col]       : 0.f;
    a1 = (k0 + 1 < 270) ? O1w[(k0 + 1) * NH + col] : 0.f;
    g_O1[w] = split2(a0, a1);

    if (kk < KKH) {
        g_M2[w] = split2(M2w[k0 * NH + col], M2w[(k0 + 1) * NH + col]);
        g_M3[w] = split2(M3w[k0 * NH + col], M3w[(k0 + 1) * NH + col]);
        g_O2[w] = split2(O2w[k0 * NH + col], O2w[(k0 + 1) * NH + col]);
    }
}

__device__ __forceinline__ void mma16816(float c[4], const unsigned a[4],
                                         unsigned b0, unsigned b1) {
    asm("mma.sync.aligned.m16n8k16.row.col.f32.bf16.bf16.f32 "
        "{%0,%1,%2,%3}, {%4,%5,%6,%7}, {%8,%9}, {%0,%1,%2,%3};"
        : "+f"(c[0]), "+f"(c[1]), "+f"(c[2]), "+f"(c[3])
        : "r"(a[0]), "r"(a[1]), "r"(a[2]), "r"(a[3]), "r"(b0), "r"(b1));
}

// ---------------------------------------------------------------------------
// One layer: O[64][256] = relu(A[64][16*kSteps] @ W + bias), split-bf16 3-MMA.
// Activation buffers, fragment-major uint2:
//   idx(mt, kk, slot, lane) = ((mt*KKS + kk)*4 + slot)*32 + lane
//   rows r = mt*16 + (lane>>2) + (slot&1)*8,
//   k-pair kp = kk*8 + (slot>>1)*4 + (lane&3) -> A[r,2kp], A[r,2kp+1]
// 16 warps; warp (wm = wid>>3, wn = wid&7) covers rows wm*32..+31
// (m-tiles 2wm, 2wm+1) and cols wn*32..+31 (4 n-tiles).
// B fragments prefetched one kk ahead; MMAs split-stage-outer.
// ---------------------------------------------------------------------------
__device__ __forceinline__ void gemm_layer(
    const uint2* __restrict__ A, int aKKS, int kSteps,
    const uint2* __restrict__ WB, const float* __restrict__ bias,
    uint2* __restrict__ O, int oKKS, int tid)
{
    const int wid  = tid >> 5;
    const int wm   = wid >> 3;
    const int wn   = wid & 7;
    const int lane = tid & 31;
    const int t    = lane & 3;

    float c[2][4][4];
#pragma unroll
    for (int m = 0; m < 2; m++)
#pragma unroll
        for (int nt = 0; nt < 4; nt++)
#pragma unroll
            for (int i = 0; i < 4; i++) c[m][nt][i] = 0.f;

    const uint2* a0p = A + (wm * 2 + 0) * aKKS * 128 + lane;
    const uint2* a1p = A + (wm * 2 + 1) * aKKS * 128 + lane;
    const uint2* wp  = WB + (wn * 4) * 64 + lane;

    unsigned bh[4][2], bl[4][2];
#pragma unroll
    for (int nt = 0; nt < 4; nt++) {
        uint2 w0 = wp[nt * 64];
        uint2 w1 = wp[nt * 64 + 32];
        bh[nt][0] = w0.x; bl[nt][0] = w0.y;
        bh[nt][1] = w1.x; bl[nt][1] = w1.y;
    }

#pragma unroll 2
    for (int kk = 0; kk < kSteps; kk++) {
        unsigned ah[2][4], al[2][4];
#pragma unroll
        for (int s = 0; s < 4; s++) {
            uint2 w0 = a0p[kk * 128 + s * 32];
            uint2 w1 = a1p[kk * 128 + s * 32];
            ah[0][s] = w0.x; al[0][s] = w0.y;
            ah[1][s] = w1.x; al[1][s] = w1.y;
        }

        // prefetch next kk's B fragments (clamped at the tail)
        unsigned nbh[4][2], nbl[4][2];
        {
            int nk = (kk + 1 < kSteps) ? kk + 1 : kk;
            const uint2* wk = wp + nk * 2048;
#pragma unroll
            for (int nt = 0; nt < 4; nt++) {
                uint2 w0 = wk[nt * 64];
                uint2 w1 = wk[nt * 64 + 32];
                nbh[nt][0] = w0.x; nbl[nt][0] = w0.y;
                nbh[nt][1] = w1.x; nbl[nt][1] = w1.y;
            }
        }

        // stage 1: hi*hi   (8 independent accumulators)
#pragma unroll
        for (int m = 0; m < 2; m++)
#pragma unroll
            for (int nt = 0; nt < 4; nt++)
                mma16816(c[m][nt], ah[m], bh[nt][0], bh[nt][1]);
        // stage 2: hi*lo
#pragma unroll
        for (int m = 0; m < 2; m++)
#pragma unroll
            for (int nt = 0; nt < 4; nt++)
                mma16816(c[m][nt], ah[m], bl[nt][0], bl[nt][1]);
        // stage 3: lo*hi
#pragma unroll
        for (int m = 0; m < 2; m++)
#pragma unroll
            for (int nt = 0; nt < 4; nt++)
                mma16816(c[m][nt], al[m], bh[nt][0], bh[nt][1]);

        // rotate prefetched B into place
#pragma unroll
        for (int nt = 0; nt < 4; nt++) {
            bh[nt][0] = nbh[nt][0]; bh[nt][1] = nbh[nt][1];
            bl[nt][0] = nbl[nt][0]; bl[nt][1] = nbl[nt][1];
        }
    }

    // Epilogue: bias + relu + split -> next layer's A-fragment layout.
    // (c0,c1) -> row g, (c2,c3) -> row g+8; kko = wn*2 + (nt>>1),
    // slot = (nt&1)*2 (+1 for row+8); lane unchanged; mt = wm*2 + m.
#pragma unroll
    for (int m = 0; m < 2; m++)
#pragma unroll
        for (int nt = 0; nt < 4; nt++) {
            int col = wn * 32 + nt * 8 + 2 * t;
            float2 bv = *(const float2*)(bias + col);
            float v0 = fmaxf(c[m][nt][0] + bv.x, 0.f);
            float v1 = fmaxf(c[m][nt][1] + bv.y, 0.f);
            float v2 = fmaxf(c[m][nt][2] + bv.x, 0.f);
            float v3 = fmaxf(c[m][nt][3] + bv.y, 0.f);
            int mt   = wm * 2 + m;
            int kko  = wn * 2 + (nt >> 1);
            int slot = (nt & 1) * 2;
            O[((mt * oKKS + kko) * 4 + slot    ) * 32 + lane] = split2(v0, v1);
            O[((mt * oKKS + kko) * 4 + slot + 1) * 32 + lane] = split2(v2, v3);
        }
}

__global__ void __launch_bounds__(NTHREADS, 1)
topdown_kernel(const float* __restrict__ towers,
               const float* __restrict__ aggregate,
               const float* __restrict__ M1b,
               const float* __restrict__ M2b,
               const float* __restrict__ M3b,
               const float* __restrict__ O1b,
               const float* __restrict__ O2b,
               const float* __restrict__ O3w, const float* __restrict__ O3b,
               float* __restrict__ out)
{
    extern __shared__ uint2 smem2[];
    uint2* X  = smem2;            // XWORDS
    uint2* H1 = X + XWORDS;       // HWORDS
    uint2* H2 = H1 + HWORDS;      // HWORDS
    float* P  = (float*)(H2 + HWORDS);

    const int tid = threadIdx.x;
    const size_t row0 = (size_t)blockIdx.x * TM;

    // tower-word decomposition for this thread (1 word per thread per step)
    const int tw_mt   = tid >> 7;            // 0..3
    const int tw_rem  = tid & 127;
    const int tw_slot = tw_rem >> 5;
    const int tw_lane = tw_rem & 31;
    const int tw_r    = tw_mt * 16 + (tw_lane >> 2) + (tw_slot & 1) * 8;
    const int tw_koff = (tw_slot >> 1) * 8 + 2 * (tw_lane & 3);
    const float* tw_base = towers + (row0 + tw_r) * (size_t)(KTOT * NIN);
    const int tw_idx = ((tw_mt * KKX + 16) * 4 + tw_slot) * 32 + tw_lane;

    // init: summary region of X (kk 0..15) from aggregate, tower(0), P = 1
    for (int w = tid; w < 4 * KKH * 4 * 32; w += NTHREADS) {
        int mt   = w >> 11;
        int rem  = w & 2047;
        int kk   = rem >> 7;
        int rem2 = rem & 127;
        int slot = rem2 >> 5;
        int lane = rem2 & 31;
        int kp   = kk * 8 + (slot >> 1) * 4 + (lane & 3);
        X[((mt * KKX + kk) * 4 + slot) * 32 + lane] =
            split2(aggregate[2 * kp], aggregate[2 * kp + 1]);
    }
    {
        const float* tp = tw_base + (size_t)(KTOT - 1) * NIN;
        float v0 = (tw_koff     < NIN) ? tp[tw_koff]     : 0.f;
        float v1 = (tw_koff + 1 < NIN) ? tp[tw_koff + 1] : 0.f;
        X[tw_idx] = split2(v0, v1);
    }
    if (tid < TM) P[tid] = 1.f;
    __syncthreads();

    for (int s = 0; s < KTOT; s++) {
        // prefetch next step's tower values into registers (used in phase 5)
        float tv0 = 0.f, tv1 = 0.f;
        if (s + 1 < KTOT) {
            const float* tp = tw_base + (size_t)(KTOT - 2 - s) * NIN;
            if (tw_koff     < NIN) tv0 = tp[tw_koff];
            if (tw_koff + 1 < NIN) tv1 = tp[tw_koff + 1];
        }

        // phase 1: O1
        gemm_layer(X,  KKX, KKX, g_O1, O1b, H1, KKH, tid);
        __syncthreads();
        // phase 2: O2
        gemm_layer(H1, KKH, KKH, g_O2, O2b, H2, KKH, tid);
        __syncthreads();

        // phase 3: O3 (reads H2, writes P) + M1 (reads X, writes H1)
        {
            int r = tid >> 3, q = tid & 7;     // 8 threads per row, 16 kp each
            int mt = r >> 4;
            int rloc = r & 15;
            int g = rloc & 7;
            int rowhi = rloc >> 3;
            float sum = 0.f;
#pragma unroll 4
            for (int kp = q * 16; kp < q * 16 + 16; kp++) {
                int kk   = kp >> 3;
                int slot = ((kp >> 2) & 1) * 2 + rowhi;
                int lane = g * 4 + (kp & 3);
                uint2 wv = H2[((mt * KKH + kk) * 4 + slot) * 32 + lane];
                float v0 = bf_lo(wv.x) + bf_lo(wv.y);
                float v1 = bf_hi(wv.x) + bf_hi(wv.y);
                float2 ww = *(const float2*)(O3w + 2 * kp);
                sum = fmaf(v0, ww.x, fmaf(v1, ww.y, sum));
            }
            sum += __shfl_xor_sync(0xffffffffu, sum, 1);
            sum += __shfl_xor_sync(0xffffffffu, sum, 2);
            sum += __shfl_xor_sync(0xffffffffu, sum, 4);
            if (q == 0) {
                float logit = sum + O3b[0];
                P[r] *= 1.f / (1.f + expf(-logit));
            }
        }
        gemm_layer(X,  KKX, KKX, g_M1, M1b, H1, KKH, tid);
        __syncthreads();   // fences O3's H2 reads before M2 writes H2

        // phase 4: M2
        gemm_layer(H1, KKH, KKH, g_M2, M2b, H2, KKH, tid);
        __syncthreads();

        // phase 5: M3 (H2 -> X kk 0..15) + tower fill for s+1 (X kk 16)
        gemm_layer(H2, KKH, KKH, g_M3, M3b, X, KKX, tid);
        if (s + 1 < KTOT)
            X[tw_idx] = split2(tv0, tv1);
        __syncthreads();
    }

    if (tid < TM) out[row0 + tid] = P[tid];
}

extern "C" void kernel_launch(void* const* d_in, const int* in_sizes, int n_in,
                              void* d_out, int out_size)
{
    const float* towers    = (const float*)d_in[0];
    const float* aggregate = (const float*)d_in[1];
    const float* M1w = (const float*)d_in[2];
    const float* M1b = (const float*)d_in[3];
    const float* M2w = (const float*)d_in[4];
    const float* M2b = (const float*)d_in[5];
    const float* M3w = (const float*)d_in[6];
    const float* M3b = (const float*)d_in[7];
    const float* O1w = (const float*)d_in[8];
    const float* O1b = (const float*)d_in[9];
    const float* O2w = (const float*)d_in[10];
    const float* O2b = (const float*)d_in[11];
    const float* O3w = (const float*)d_in[12];
    const float* O3b = (const float*)d_in[13];
    float* out = (float*)d_out;

    const int N = in_sizes[0] / (KTOT * NIN);   // 131072

    prep_weights<<<(KKX * 2048 + 255) / 256, 256>>>(M1w, O1w, M2w, M3w, O2w);

    const size_t smem_bytes =
        (size_t)(XWORDS + 2 * HWORDS) * sizeof(uint2) + TM * sizeof(float);
    cudaFuncSetAttribute(topdown_kernel,
                         cudaFuncAttributeMaxDynamicSharedMemorySize,
                         (int)smem_bytes);

    topdown_kernel<<<N / TM, NTHREADS, smem_bytes>>>(
        towers, aggregate,
        M1b, M2b, M3b,
        O1b, O2b,
        O3w, O3b,
        out);
}